// round 15
// baseline (speedup 1.0000x reference)
#include <cuda_runtime.h>
#include <cuda_fp16.h>
#include <cstdint>

#define NN 50000
#define NE 400000
#define DD 512
#define LL 3
#define BM 128
#define BN 128
#define NCHK 32            /* k chunks of 32 over K=1024 ([agg | z]) */
#define PAD 40             /* ELL width; P(deg>=40 | Poisson(8)) ~ 6e-16 */

/* smem u32 word offsets: pair-packed tiles, stride 136 everywhere */
#define AHI_W 0             /* 16 kpairs x 136 = 2176 words */
#define BHI_W 2176          /* 16 kpairs x 136 = 2176 words */
#define BLO_W 4352          /* + 2176 */
#define SMEM_WORDS 6528     /* 26.1 KB per CTA -> 2 CTAs/SM */

/* prep0 block ranges */
#define B0_ZERO 1
#define B0_PREPB 197
#define B0_XH 3269          /* 197 + 3072 */
#define B0_TOTAL 9519       /* 3269 + 6250 */

// ---------------- device scratch (no allocs allowed) ----------------
__device__ float g_agg[(size_t)NN * DD];
__device__ float g_z1[(size_t)NN * DD];
__device__ float g_z2[(size_t)NN * DD];
__device__ __align__(16) uint32_t g_xh[(size_t)NN * 256];    // fp16-pair x
__device__ __align__(16) uint32_t g_zh1[(size_t)NN * 256];   // fp16-pair z1
__device__ __align__(16) uint32_t g_zh2[(size_t)NN * 256];   // fp16-pair z2
__device__ __align__(16) uint32_t g_Bh16[(size_t)LL * 512 * 512];  // 3 MB
__device__ __align__(16) uint32_t g_Bl16[(size_t)LL * 512 * 512];  // 3 MB
__device__ int   g_degi[NN];
__device__ int   g_ell_src[(size_t)NN * PAD];
__device__ float g_ell_w[(size_t)NN * PAD];
__device__ int   g_is32;

// ---------------- helpers ----------------
__device__ __forceinline__ unsigned pack_h2(float v0, float v1) {
    __half2 h = __floats2half2_rn(v0, v1);
    return *reinterpret_cast<unsigned*>(&h);
}
__device__ __forceinline__ void split_pack_f16(float v0, float v1, unsigned& hw, unsigned& lw) {
    __half h0 = __float2half_rn(v0), h1 = __float2half_rn(v1);
    float l0 = v0 - __half2float(h0), l1 = v1 - __half2float(h1);
    __half2 hh = __halves2half2(h0, h1);
    hw = *reinterpret_cast<unsigned*>(&hh);
    lw = pack_h2(l0, l1);
}
__device__ __forceinline__ uint32_t smem_u32(const void* p) {
    uint32_t a;
    asm("{ .reg .u64 t; cvta.to.shared.u64 t, %1; cvt.u32.u64 %0, t; }" : "=r"(a) : "l"(p));
    return a;
}

#define CPASYNC16(dst, src) \
    asm volatile("cp.async.cg.shared.global [%0], [%1], 16;" :: "r"(dst), "l"(src))
#define MMA16816(d, a, b0, b1)                                                    \
    asm volatile("mma.sync.aligned.m16n8k16.row.col.f32.f16.f16.f32 "             \
                 "{%0,%1,%2,%3}, {%4,%5,%6,%7}, {%8,%9}, {%0,%1,%2,%3};"          \
                 : "+f"((d)[0]), "+f"((d)[1]), "+f"((d)[2]), "+f"((d)[3])         \
                 : "r"((a)[0]), "r"((a)[1]), "r"((a)[2]), "r"((a)[3]),            \
                   "r"(b0), "r"(b1))

// ---------------- prep0: detect + zero degi + prep B + x->fp16 (fused) ------
__global__ void prep0_kernel(const unsigned int* __restrict__ raw,
                             const float* __restrict__ x,
                             const float* __restrict__ Wl,
                             const float* __restrict__ Wr) {
    int b = blockIdx.x, t = threadIdx.x;
    if (b == 0) {
        __shared__ unsigned sacc[256];
        unsigned acc = 0;
        for (int j = t; j < 4096; j += 256) acc |= raw[2 * j + 1];
        sacc[t] = acc;
        __syncthreads();
        for (int s = 128; s > 0; s >>= 1) {
            if (t < s) sacc[t] |= sacc[t + s];
            __syncthreads();
        }
        if (t == 0) g_is32 = (sacc[0] != 0) ? 1 : 0;
    } else if (b < B0_PREPB) {
        int i = (b - B0_ZERO) * 256 + t;
        if (i < NN) g_degi[i] = 0;
    } else if (b < B0_XH) {
        // B precompute: [l][kpair(512)][n(512)] fp16 hi/lo pairs
        int u = (b - B0_PREPB) * 256 + t;          // < LL*512*512
        int n = u & 511;
        int kp = (u >> 9) & 511;
        int l = u >> 18;
        int k = 2 * kp;
        const float* W = (k < DD) ? (Wl + (size_t)l * DD * DD + (size_t)k * DD)
                                  : (Wr + (size_t)l * DD * DD + (size_t)(k - DD) * DD);
        float v0 = W[n], v1 = W[DD + n];
        unsigned hw, lw;
        split_pack_f16(v0, v1, hw, lw);
        size_t idx = ((size_t)l * 512 + kp) * 512 + n;
        g_Bh16[idx] = hw;
        g_Bl16[idx] = lw;
    } else {
        size_t w0 = ((size_t)(b - B0_XH) * 256 + t) * 8;
        if (w0 < (size_t)NN * 256) {
            const float2* xs = (const float2*)x + w0;
#pragma unroll
            for (int q = 0; q < 8; q++) {
                float2 f = xs[q];
                g_xh[w0 + q] = pack_h2(f.x, f.y);
            }
        }
    }
}

// ---------------- build ELL: decode edge, slot via atomicAdd ----------------
__global__ void build_ell_kernel(const void* __restrict__ raw,
                                 const float* __restrict__ ew) {
    int e = blockIdx.x * blockDim.x + threadIdx.x;
    if (e >= NE) return;
    int s, d;
    if (g_is32) {
        const int* p = (const int*)raw;
        s = p[e]; d = p[NE + e];
    } else {
        const long long* p = (const long long*)raw;
        s = (int)p[e]; d = (int)p[NE + e];
    }
    int slot = atomicAdd(&g_degi[d], 1);
    if (slot < PAD) {
        g_ell_src[(size_t)d * PAD + slot] = s;
        g_ell_w[(size_t)d * PAD + slot] = ew[e];
    }
}

// ---------------- gather (fp16 input): agg[d] = mean_e w_e * z[src_e] -------
__global__ void __launch_bounds__(128) gather_kernel(int insel) {
    const uint32_t* zh = (insel == 0) ? g_xh : (insel == 1 ? g_zh1 : g_zh2);
    int d = blockIdx.x, t = threadIdx.x;
    int deg = g_degi[d];
    int dg = (deg < PAD) ? deg : PAD;
    const int* esrc = g_ell_src + (size_t)d * PAD;
    const float* ewp = g_ell_w + (size_t)d * PAD;
    float4 a0 = make_float4(0.f, 0.f, 0.f, 0.f);
    float4 a1 = make_float4(0.f, 0.f, 0.f, 0.f);
    int j = 0;
    for (; j + 1 < dg; j += 2) {
        int s0 = __ldg(&esrc[j]);
        int s1 = __ldg(&esrc[j + 1]);
        float w0 = __ldg(&ewp[j]);
        float w1 = __ldg(&ewp[j + 1]);
        uint2 p0 = ((const uint2*)(zh + (size_t)s0 * 256))[t];
        uint2 p1 = ((const uint2*)(zh + (size_t)s1 * 256))[t];
        float2 u00 = __half22float2(*(__half2*)&p0.x);
        float2 u01 = __half22float2(*(__half2*)&p0.y);
        float2 u10 = __half22float2(*(__half2*)&p1.x);
        float2 u11 = __half22float2(*(__half2*)&p1.y);
        a0.x += w0 * u00.x; a0.y += w0 * u00.y;
        a0.z += w0 * u01.x; a0.w += w0 * u01.y;
        a1.x += w1 * u10.x; a1.y += w1 * u10.y;
        a1.z += w1 * u11.x; a1.w += w1 * u11.y;
    }
    if (j < dg) {
        int s0 = __ldg(&esrc[j]);
        float w0 = __ldg(&ewp[j]);
        uint2 p0 = ((const uint2*)(zh + (size_t)s0 * 256))[t];
        float2 u00 = __half22float2(*(__half2*)&p0.x);
        float2 u01 = __half22float2(*(__half2*)&p0.y);
        a0.x += w0 * u00.x; a0.y += w0 * u00.y;
        a0.z += w0 * u01.x; a0.w += w0 * u01.y;
    }
    float inv = (deg > 0) ? 1.0f / (float)deg : 0.0f;
    a0.x = (a0.x + a1.x) * inv;
    a0.y = (a0.y + a1.y) * inv;
    a0.z = (a0.z + a1.z) * inv;
    a0.w = (a0.w + a1.w) * inv;
    ((float4*)(g_agg + (size_t)d * DD))[t] = a0;
}

// ---------------- GEMM: 128 thr, 4 warps of 64x64, 2 CTAs/SM ----------------
__global__ void __launch_bounds__(128, 2) gemm_kernel(
    const float* __restrict__ xext, int insel, int layer,
    const float* __restrict__ bias,
    float* __restrict__ outext, int outsel) {
    const float* zsrc = (insel == 0) ? xext : (insel == 1 ? g_z1 : g_z2);
    float* zout = (outsel == 0) ? g_z1 : (outsel == 1 ? g_z2 : outext);
    uint32_t* zhout = (outsel == 0) ? g_zh1 : g_zh2;

    __shared__ uint32_t sw[SMEM_WORDS];
    uint32_t sbase = smem_u32(sw);
    int tid = threadIdx.x, lane = tid & 31, warp = tid >> 5;
    int wm = warp >> 1, wn = warp & 1;          // 2x2 grid of 64x64 tiles
    int m0 = blockIdx.y * BM, n0 = blockIdx.x * BN;
    int g = lane >> 2, c = lane & 3;

    float acc[4][8][4];
#pragma unroll
    for (int i = 0; i < 4; i++)
#pragma unroll
        for (int j = 0; j < 8; j++)
#pragma unroll
            for (int q = 0; q < 4; q++) acc[i][j][q] = 0.0f;

    // A loader: one row per thread, full 32-k chunk
    int am = m0 + tid;
    int amc = (am < NN) ? am : (NN - 1);
    const float* aggrow = g_agg + (size_t)amc * DD;
    const float* zrow = zsrc + (size_t)amc * DD;
    // B loader: thread -> (kpair bp = tid>>3 (0..15), word offset (tid&7)*16)
    int bp = tid >> 3;
    int bnw = (tid & 7) * 16;
    const uint32_t* Bh = g_Bh16 + ((size_t)layer * 512 + bp) * 512 + n0 + bnw;
    const uint32_t* Bl = g_Bl16 + ((size_t)layer * 512 + bp) * 512 + n0 + bnw;
    uint32_t bh_dst = sbase + (BHI_W + bp * 136 + bnw) * 4;
    uint32_t bl_dst = sbase + (BLO_W + bp * 136 + bnw) * 4;

    float fA[32];
    auto load_regs = [&](int kc) {
        const float* ap = (kc < 16) ? (aggrow + kc * 32) : (zrow + (kc - 16) * 32);
#pragma unroll
        for (int q = 0; q < 8; q++) {
            float4 f = ((const float4*)ap)[q];
            fA[4 * q] = f.x; fA[4 * q + 1] = f.y;
            fA[4 * q + 2] = f.z; fA[4 * q + 3] = f.w;
        }
    };

    load_regs(0);

    for (int kc = 0; kc < NCHK; kc++) {
        __syncthreads();   // consumers of previous chunk done
        // ---- B: stream pre-converted fp16 tiles straight to smem
        {
            const uint32_t* bh = Bh + (size_t)kc * (16 * 512);
            const uint32_t* bl = Bl + (size_t)kc * (16 * 512);
#pragma unroll
            for (int q = 0; q < 4; q++) {
                CPASYNC16(bh_dst + q * 16, bh + q * 4);
                CPASYNC16(bl_dst + q * 16, bl + q * 4);
            }
            asm volatile("cp.async.commit_group;");
        }
        // ---- A: pack fp16 pairs from prefetched regs (16 kpairs, own row)
        {
#pragma unroll
            for (int e = 0; e < 16; e++)
                sw[AHI_W + e * 136 + tid] = pack_h2(fA[2 * e], fA[2 * e + 1]);
        }
        asm volatile("cp.async.wait_group 0;");
        __syncthreads();
        if (kc + 1 < NCHK) load_regs(kc + 1);   // prefetch overlaps mma below
        // ---- compute: 2 x k16, 2 products each (warp tile 64x64)
#pragma unroll
        for (int ks = 0; ks < 2; ks++) {
            int ab = (8 * ks + c) * 136 + wm * 64 + g;
            int bb = (8 * ks + c) * 136 + wn * 64 + g;
            uint32_t af[4][4], bf2[4][4];
#pragma unroll
            for (int i = 0; i < 4; i++) {
                int x = AHI_W + ab + i * 16;
                af[i][0] = sw[x]; af[i][1] = sw[x + 8];
                af[i][2] = sw[x + 544]; af[i][3] = sw[x + 552];
            }
            // P1: Ahi x Bhi
#pragma unroll
            for (int j = 0; j < 4; j++) {
                int x = BHI_W + bb + j * 16;
                bf2[j][0] = sw[x]; bf2[j][1] = sw[x + 544];
                bf2[j][2] = sw[x + 8]; bf2[j][3] = sw[x + 552];
            }
#pragma unroll
            for (int i = 0; i < 4; i++)
#pragma unroll
                for (int j = 0; j < 4; j++) {
                    MMA16816(acc[i][2 * j], af[i], bf2[j][0], bf2[j][1]);
                    MMA16816(acc[i][2 * j + 1], af[i], bf2[j][2], bf2[j][3]);
                }
            // P2: Ahi x Blo
#pragma unroll
            for (int j = 0; j < 4; j++) {
                int x = BLO_W + bb + j * 16;
                bf2[j][0] = sw[x]; bf2[j][1] = sw[x + 544];
                bf2[j][2] = sw[x + 8]; bf2[j][3] = sw[x + 552];
            }
#pragma unroll
            for (int i = 0; i < 4; i++)
#pragma unroll
                for (int j = 0; j < 4; j++) {
                    MMA16816(acc[i][2 * j], af[i], bf2[j][0], bf2[j][1]);
                    MMA16816(acc[i][2 * j + 1], af[i], bf2[j][2], bf2[j][3]);
                }
        }
    }

    // ---- epilogue: bias + relu; fp32 store + fp16-pair store for next gather
    int cc = c << 1;
    float bj0[8], bj1[8];
#pragma unroll
    for (int j = 0; j < 8; j++) {
        int col = n0 + wn * 64 + j * 8 + cc;
        bj0[j] = __ldg(bias + col);
        bj1[j] = __ldg(bias + col + 1);
    }
#pragma unroll
    for (int i = 0; i < 4; i++) {
        int r0 = m0 + wm * 64 + i * 16 + g;
#pragma unroll
        for (int j = 0; j < 8; j++) {
            int col = n0 + wn * 64 + j * 8 + cc;
            float v00 = fmaxf(acc[i][j][0] + bj0[j], 0.0f);
            float v01 = fmaxf(acc[i][j][1] + bj1[j], 0.0f);
            float v10 = fmaxf(acc[i][j][2] + bj0[j], 0.0f);
            float v11 = fmaxf(acc[i][j][3] + bj1[j], 0.0f);
            if (r0 < NN) {
                *(float2*)(zout + (size_t)r0 * DD + col) = make_float2(v00, v01);
                if (outsel != 2)
                    zhout[(size_t)r0 * 256 + (col >> 1)] = pack_h2(v00, v01);
            }
            if (r0 + 8 < NN) {
                *(float2*)(zout + (size_t)(r0 + 8) * DD + col) = make_float2(v10, v11);
                if (outsel != 2)
                    zhout[(size_t)(r0 + 8) * 256 + (col >> 1)] = pack_h2(v10, v11);
            }
        }
    }
}

// ---------------- launch ----------------
extern "C" void kernel_launch(void* const* d_in, const int* in_sizes, int n_in,
                              void* d_out, int out_size) {
    (void)in_sizes; (void)n_in; (void)out_size;
    const float* x  = (const float*)d_in[0];
    const void*  ei = d_in[1];
    const float* ew = (const float*)d_in[2];
    const float* Wl = (const float*)d_in[3];
    const float* Wr = (const float*)d_in[4];
    const float* b  = (const float*)d_in[5];
    float* out = (float*)d_out;

    prep0_kernel<<<B0_TOTAL, 256>>>((const unsigned int*)ei, x, Wl, Wr);
    build_ell_kernel<<<(NE + 255) / 256, 256>>>(ei, ew);

    dim3 ggrid(4, (NN + BM - 1) / BM);   // n-blocks x m-tiles

    // layer 0: x -> g_z1 ; layer 1: g_z1 -> g_z2 ; layer 2: g_z2 -> out
    for (int l = 0; l < LL; l++) {
        int insel  = (l == 0) ? 0 : l;        // 0:x/g_xh 1:z1 2:z2
        int outsel = (l == LL - 1) ? 2 : l;   // 0:z1 1:z2 2:external
        gather_kernel<<<NN, 128>>>(insel);
        gemm_kernel<<<ggrid, 128>>>(x, insel, l,
                                    b + (size_t)l * DD,
                                    out, outsel);
    }
}

// round 16
// speedup vs baseline: 1.2844x; 1.2844x over previous
#include <cuda_runtime.h>
#include <cuda_fp16.h>
#include <cstdint>

#define NN 50000
#define NE 400000
#define DD 512
#define LL 3
#define BM 128
#define BN 128
#define NCHK 32            /* k chunks of 32 over K=1024 ([agg | z]) */
#define PAD 40             /* ELL width; P(deg>=40 | Poisson(8)) ~ 6e-16 */

/* smem u32 word offsets: A row-major stride 20; B kpair-major stride 136 */
#define A_W 0               /* 128 rows x 20 = 2560 words */
#define BHI_W 2560          /* 16 kpairs x 136 = 2176 words */
#define BLO_W 4736          /* + 2176 */
#define SMEM_WORDS 6912     /* 27.6 KB per CTA -> 2 CTAs/SM */

/* prep0 block ranges */
#define B0_ZERO 1
#define B0_PREPB 197
#define B0_XH 3269          /* 197 + 3072 */
#define B0_TOTAL 9519       /* 3269 + 6250 */

// ---------------- device scratch (no allocs allowed) ----------------
__device__ __align__(16) uint32_t g_aggh[(size_t)NN * 256];  // fp16-pair agg
__device__ __align__(16) uint32_t g_xh[(size_t)NN * 256];    // fp16-pair x
__device__ __align__(16) uint32_t g_zhA[(size_t)NN * 256];   // fp16-pair z slot A
__device__ __align__(16) uint32_t g_zhB[(size_t)NN * 256];   // fp16-pair z slot B
__device__ __align__(16) uint32_t g_Bh16[(size_t)LL * 512 * 512];  // 3 MB
__device__ __align__(16) uint32_t g_Bl16[(size_t)LL * 512 * 512];  // 3 MB
__device__ int   g_degi[NN];
__device__ int   g_ell_src[(size_t)NN * PAD];
__device__ float g_ell_w[(size_t)NN * PAD];
__device__ int   g_is32;

// ---------------- helpers ----------------
__device__ __forceinline__ unsigned pack_h2(float v0, float v1) {
    __half2 h = __floats2half2_rn(v0, v1);
    return *reinterpret_cast<unsigned*>(&h);
}
__device__ __forceinline__ void split_pack_f16(float v0, float v1, unsigned& hw, unsigned& lw) {
    __half h0 = __float2half_rn(v0), h1 = __float2half_rn(v1);
    float l0 = v0 - __half2float(h0), l1 = v1 - __half2float(h1);
    __half2 hh = __halves2half2(h0, h1);
    hw = *reinterpret_cast<unsigned*>(&hh);
    lw = pack_h2(l0, l1);
}
__device__ __forceinline__ uint32_t smem_u32(const void* p) {
    uint32_t a;
    asm("{ .reg .u64 t; cvta.to.shared.u64 t, %1; cvt.u32.u64 %0, t; }" : "=r"(a) : "l"(p));
    return a;
}

#define CPASYNC16(dst, src) \
    asm volatile("cp.async.cg.shared.global [%0], [%1], 16;" :: "r"(dst), "l"(src))
#define MMA16816(d, a, b0, b1)                                                    \
    asm volatile("mma.sync.aligned.m16n8k16.row.col.f32.f16.f16.f32 "             \
                 "{%0,%1,%2,%3}, {%4,%5,%6,%7}, {%8,%9}, {%0,%1,%2,%3};"          \
                 : "+f"((d)[0]), "+f"((d)[1]), "+f"((d)[2]), "+f"((d)[3])         \
                 : "r"((a)[0]), "r"((a)[1]), "r"((a)[2]), "r"((a)[3]),            \
                   "r"(b0), "r"(b1))

// ---------------- prep0: detect + zero degi + prep B + x->fp16 (fused) ------
__global__ void prep0_kernel(const unsigned int* __restrict__ raw,
                             const float* __restrict__ x,
                             const float* __restrict__ Wl,
                             const float* __restrict__ Wr) {
    int b = blockIdx.x, t = threadIdx.x;
    if (b == 0) {
        __shared__ unsigned sacc[256];
        unsigned acc = 0;
        for (int j = t; j < 4096; j += 256) acc |= raw[2 * j + 1];
        sacc[t] = acc;
        __syncthreads();
        for (int s = 128; s > 0; s >>= 1) {
            if (t < s) sacc[t] |= sacc[t + s];
            __syncthreads();
        }
        if (t == 0) g_is32 = (sacc[0] != 0) ? 1 : 0;
    } else if (b < B0_PREPB) {
        int i = (b - B0_ZERO) * 256 + t;
        if (i < NN) g_degi[i] = 0;
    } else if (b < B0_XH) {
        // B precompute: [l][kpair(512)][n(512)] fp16 hi/lo pairs
        int u = (b - B0_PREPB) * 256 + t;          // < LL*512*512
        int n = u & 511;
        int kp = (u >> 9) & 511;
        int l = u >> 18;
        int k = 2 * kp;
        const float* W = (k < DD) ? (Wl + (size_t)l * DD * DD + (size_t)k * DD)
                                  : (Wr + (size_t)l * DD * DD + (size_t)(k - DD) * DD);
        float v0 = W[n], v1 = W[DD + n];
        unsigned hw, lw;
        split_pack_f16(v0, v1, hw, lw);
        size_t idx = ((size_t)l * 512 + kp) * 512 + n;
        g_Bh16[idx] = hw;
        g_Bl16[idx] = lw;
    } else {
        size_t w0 = ((size_t)(b - B0_XH) * 256 + t) * 8;
        if (w0 < (size_t)NN * 256) {
            const float2* xs = (const float2*)x + w0;
#pragma unroll
            for (int q = 0; q < 8; q++) {
                float2 f = xs[q];
                g_xh[w0 + q] = pack_h2(f.x, f.y);
            }
        }
    }
}

// ---------------- build ELL: decode edge, slot via atomicAdd ----------------
__global__ void build_ell_kernel(const void* __restrict__ raw,
                                 const float* __restrict__ ew) {
    int e = blockIdx.x * blockDim.x + threadIdx.x;
    if (e >= NE) return;
    int s, d;
    if (g_is32) {
        const int* p = (const int*)raw;
        s = p[e]; d = p[NE + e];
    } else {
        const long long* p = (const long long*)raw;
        s = (int)p[e]; d = (int)p[NE + e];
    }
    int slot = atomicAdd(&g_degi[d], 1);
    if (slot < PAD) {
        g_ell_src[(size_t)d * PAD + slot] = s;
        g_ell_w[(size_t)d * PAD + slot] = ew[e];
    }
}

// ---------------- gather: aggh[d] = pack_f16( mean_e w_e * z[src_e] ) -------
__global__ void __launch_bounds__(128) gather_kernel(int insel) {
    const uint32_t* zh = (insel == 0) ? g_xh : (insel == 1 ? g_zhA : g_zhB);
    int d = blockIdx.x, t = threadIdx.x;
    int deg = g_degi[d];
    int dg = (deg < PAD) ? deg : PAD;
    const int* esrc = g_ell_src + (size_t)d * PAD;
    const float* ewp = g_ell_w + (size_t)d * PAD;
    float4 a0 = make_float4(0.f, 0.f, 0.f, 0.f);
    float4 a1 = make_float4(0.f, 0.f, 0.f, 0.f);
    int j = 0;
    for (; j + 1 < dg; j += 2) {
        int s0 = __ldg(&esrc[j]);
        int s1 = __ldg(&esrc[j + 1]);
        float w0 = __ldg(&ewp[j]);
        float w1 = __ldg(&ewp[j + 1]);
        uint2 p0 = ((const uint2*)(zh + (size_t)s0 * 256))[t];
        uint2 p1 = ((const uint2*)(zh + (size_t)s1 * 256))[t];
        float2 u00 = __half22float2(*(__half2*)&p0.x);
        float2 u01 = __half22float2(*(__half2*)&p0.y);
        float2 u10 = __half22float2(*(__half2*)&p1.x);
        float2 u11 = __half22float2(*(__half2*)&p1.y);
        a0.x += w0 * u00.x; a0.y += w0 * u00.y;
        a0.z += w0 * u01.x; a0.w += w0 * u01.y;
        a1.x += w1 * u10.x; a1.y += w1 * u10.y;
        a1.z += w1 * u11.x; a1.w += w1 * u11.y;
    }
    if (j < dg) {
        int s0 = __ldg(&esrc[j]);
        float w0 = __ldg(&ewp[j]);
        uint2 p0 = ((const uint2*)(zh + (size_t)s0 * 256))[t];
        float2 u00 = __half22float2(*(__half2*)&p0.x);
        float2 u01 = __half22float2(*(__half2*)&p0.y);
        a0.x += w0 * u00.x; a0.y += w0 * u00.y;
        a0.z += w0 * u01.x; a0.w += w0 * u01.y;
    }
    float inv = (deg > 0) ? 1.0f / (float)deg : 0.0f;
    a0.x = (a0.x + a1.x) * inv;
    a0.y = (a0.y + a1.y) * inv;
    a0.z = (a0.z + a1.z) * inv;
    a0.w = (a0.w + a1.w) * inv;
    uint2 pk;
    pk.x = pack_h2(a0.x, a0.y);
    pk.y = pack_h2(a0.z, a0.w);
    ((uint2*)(g_aggh + (size_t)d * 256))[t] = pk;
}

// ---------------- GEMM: all-streamed fp16 A+B, 8 warps 32x64, 2 CTAs/SM -----
__global__ void __launch_bounds__(256, 2) gemm_kernel(
    int zsel, int layer,
    const float* __restrict__ bias,
    float* __restrict__ outext, int outsel) {
    const uint32_t* zhin = (zsel == 0) ? g_xh : (zsel == 1 ? g_zhA : g_zhB);
    uint32_t* zhout = (outsel == 0) ? g_zhA : g_zhB;   // unused when outsel==2

    __shared__ uint32_t sw[SMEM_WORDS];
    uint32_t sbase = smem_u32(sw);
    int tid = threadIdx.x, lane = tid & 31, warp = tid >> 5;
    int wm = warp >> 1, wn = warp & 1;          // 4x2 grid of 32x64 tiles
    int m0 = blockIdx.y * BM, n0 = blockIdx.x * BN;
    int g = lane >> 2, c = lane & 3;

    float acc[2][8][4];
#pragma unroll
    for (int i = 0; i < 2; i++)
#pragma unroll
        for (int j = 0; j < 8; j++)
#pragma unroll
            for (int q = 0; q < 4; q++) acc[i][j][q] = 0.0f;

    // A loader: thread -> (row ar = tid>>1, half ah = tid&1 -> 8 words)
    int ar = tid >> 1;
    int ah = tid & 1;
    int am = m0 + ar;
    int amc = (am < NN) ? am : (NN - 1);
    const uint32_t* Aagg = g_aggh + (size_t)amc * 256 + ah * 8;
    const uint32_t* Az   = zhin   + (size_t)amc * 256 + ah * 8;
    uint32_t a_dst = sbase + (A_W + ar * 20 + ah * 8) * 4;
    // B loader: thread -> (kpair bp = tid>>4 (0..15), word offset (tid&15)*8)
    int bp = tid >> 4;
    int bnw = (tid & 15) * 8;
    const uint32_t* Bh = g_Bh16 + ((size_t)layer * 512 + bp) * 512 + n0 + bnw;
    const uint32_t* Bl = g_Bl16 + ((size_t)layer * 512 + bp) * 512 + n0 + bnw;
    uint32_t bh_dst = sbase + (BHI_W + bp * 136 + bnw) * 4;
    uint32_t bl_dst = sbase + (BLO_W + bp * 136 + bnw) * 4;

    for (int kc = 0; kc < NCHK; kc++) {
        __syncthreads();   // consumers of previous chunk done
        // ---- A + B: stream pre-packed fp16 tiles straight to smem
        {
            const uint32_t* as = (kc < 16) ? (Aagg + kc * 16) : (Az + (kc - 16) * 16);
            CPASYNC16(a_dst, as);
            CPASYNC16(a_dst + 16, as + 4);
            const uint32_t* bh = Bh + (size_t)kc * (16 * 512);
            const uint32_t* bl = Bl + (size_t)kc * (16 * 512);
            CPASYNC16(bh_dst, bh);
            CPASYNC16(bh_dst + 16, bh + 4);
            CPASYNC16(bl_dst, bl);
            CPASYNC16(bl_dst + 16, bl + 4);
            asm volatile("cp.async.commit_group;");
        }
        asm volatile("cp.async.wait_group 0;");
        __syncthreads();
        // ---- compute: 2 x k16, 2 products each (warp tile 32x64)
#pragma unroll
        for (int ks = 0; ks < 2; ks++) {
            int ab = A_W + (wm * 32 + g) * 20 + 8 * ks + c;
            int bb = (8 * ks + c) * 136 + wn * 64 + g;
            uint32_t af[2][4], bf2[4][4];
#pragma unroll
            for (int i = 0; i < 2; i++) {
                int x = ab + i * 320;        // row + 16i
                af[i][0] = sw[x];            // (row, kp)
                af[i][1] = sw[x + 160];      // (row+8, kp)
                af[i][2] = sw[x + 4];        // (row, kp+4)
                af[i][3] = sw[x + 164];      // (row+8, kp+4)
            }
            // P1: Ahi x Bhi
#pragma unroll
            for (int j = 0; j < 4; j++) {
                int x = BHI_W + bb + j * 16;
                bf2[j][0] = sw[x]; bf2[j][1] = sw[x + 544];
                bf2[j][2] = sw[x + 8]; bf2[j][3] = sw[x + 552];
            }
#pragma unroll
            for (int i = 0; i < 2; i++)
#pragma unroll
                for (int j = 0; j < 4; j++) {
                    MMA16816(acc[i][2 * j], af[i], bf2[j][0], bf2[j][1]);
                    MMA16816(acc[i][2 * j + 1], af[i], bf2[j][2], bf2[j][3]);
                }
            // P2: Ahi x Blo
#pragma unroll
            for (int j = 0; j < 4; j++) {
                int x = BLO_W + bb + j * 16;
                bf2[j][0] = sw[x]; bf2[j][1] = sw[x + 544];
                bf2[j][2] = sw[x + 8]; bf2[j][3] = sw[x + 552];
            }
#pragma unroll
            for (int i = 0; i < 2; i++)
#pragma unroll
                for (int j = 0; j < 4; j++) {
                    MMA16816(acc[i][2 * j], af[i], bf2[j][0], bf2[j][1]);
                    MMA16816(acc[i][2 * j + 1], af[i], bf2[j][2], bf2[j][3]);
                }
        }
    }

    // ---- epilogue: bias + relu; fp16-pair z (or fp32 out on last layer)
    int cc = c << 1;
    float bj0[8], bj1[8];
#pragma unroll
    for (int j = 0; j < 8; j++) {
        int col = n0 + wn * 64 + j * 8 + cc;
        bj0[j] = __ldg(bias + col);
        bj1[j] = __ldg(bias + col + 1);
    }
#pragma unroll
    for (int i = 0; i < 2; i++) {
        int r0 = m0 + wm * 32 + i * 16 + g;
#pragma unroll
        for (int j = 0; j < 8; j++) {
            int col = n0 + wn * 64 + j * 8 + cc;
            float v00 = fmaxf(acc[i][j][0] + bj0[j], 0.0f);
            float v01 = fmaxf(acc[i][j][1] + bj1[j], 0.0f);
            float v10 = fmaxf(acc[i][j][2] + bj0[j], 0.0f);
            float v11 = fmaxf(acc[i][j][3] + bj1[j], 0.0f);
            if (outsel == 2) {
                if (r0 < NN)
                    *(float2*)(outext + (size_t)r0 * DD + col) = make_float2(v00, v01);
                if (r0 + 8 < NN)
                    *(float2*)(outext + (size_t)(r0 + 8) * DD + col) = make_float2(v10, v11);
            } else {
                if (r0 < NN)
                    zhout[(size_t)r0 * 256 + (col >> 1)] = pack_h2(v00, v01);
                if (r0 + 8 < NN)
                    zhout[(size_t)(r0 + 8) * 256 + (col >> 1)] = pack_h2(v10, v11);
            }
        }
    }
}

// ---------------- launch ----------------
extern "C" void kernel_launch(void* const* d_in, const int* in_sizes, int n_in,
                              void* d_out, int out_size) {
    (void)in_sizes; (void)n_in; (void)out_size;
    const float* x  = (const float*)d_in[0];
    const void*  ei = d_in[1];
    const float* ew = (const float*)d_in[2];
    const float* Wl = (const float*)d_in[3];
    const float* Wr = (const float*)d_in[4];
    const float* b  = (const float*)d_in[5];
    float* out = (float*)d_out;

    prep0_kernel<<<B0_TOTAL, 256>>>((const unsigned int*)ei, x, Wl, Wr);
    build_ell_kernel<<<(NE + 255) / 256, 256>>>(ei, ew);

    dim3 ggrid(4, (NN + BM - 1) / BM);   // n-blocks x m-tiles

    // z chain: xh -> zhA -> zhB -> out(fp32)
    for (int l = 0; l < LL; l++) {
        int zsel   = l;                      // 0:xh 1:zhA 2:zhB
        int outsel = (l == LL - 1) ? 2 : l;  // 0:zhA 1:zhB 2:external fp32
        gather_kernel<<<NN, 128>>>(zsel);
        gemm_kernel<<<ggrid, 256>>>(zsel, l,
                                    b + (size_t)l * DD,
                                    out, outsel);
    }
}

// round 17
// speedup vs baseline: 1.3362x; 1.0403x over previous
#include <cuda_runtime.h>
#include <cuda_fp16.h>
#include <cstdint>

#define NN 50000
#define NE 400000
#define DD 512
#define LL 3
#define BM 128
#define BN 128
#define NCHK 32            /* k chunks of 32 over K=1024 ([agg | z]) */
#define PAD 40             /* ELL width; P(deg>=40 | Poisson(8)) ~ 6e-16 */

/* smem u32 word offsets within a slot: A stride 20; B stride 136 */
#define A_W 0               /* 128 rows x 20 = 2560 words */
#define BHI_W 2560          /* 16 kpairs x 136 = 2176 words */
#define BLO_W 4736          /* + 2176 */
#define SLOT_W 6912         /* words per slot */
#define SMEM_BYTES (2 * SLOT_W * 4)   /* 55296 B -> 2 CTAs/SM */

/* prep0 block ranges */
#define B0_ZERO 1
#define B0_PREPB 197
#define B0_XH 3269          /* 197 + 3072 */
#define B0_TOTAL 9519       /* 3269 + 6250 */

// ---------------- device scratch (no allocs allowed) ----------------
__device__ __align__(16) uint32_t g_aggh[(size_t)NN * 256];  // fp16-pair agg
__device__ __align__(16) uint32_t g_xh[(size_t)NN * 256];    // fp16-pair x
__device__ __align__(16) uint32_t g_zhA[(size_t)NN * 256];   // fp16-pair z slot A
__device__ __align__(16) uint32_t g_zhB[(size_t)NN * 256];   // fp16-pair z slot B
__device__ __align__(16) uint32_t g_Bh16[(size_t)LL * 512 * 512];  // 3 MB
__device__ __align__(16) uint32_t g_Bl16[(size_t)LL * 512 * 512];  // 3 MB
__device__ int   g_degi[NN];
__device__ int   g_ell_src[(size_t)NN * PAD];
__device__ float g_ell_w[(size_t)NN * PAD];
__device__ int   g_is32;

// ---------------- helpers ----------------
__device__ __forceinline__ unsigned pack_h2(float v0, float v1) {
    __half2 h = __floats2half2_rn(v0, v1);
    return *reinterpret_cast<unsigned*>(&h);
}
__device__ __forceinline__ void split_pack_f16(float v0, float v1, unsigned& hw, unsigned& lw) {
    __half h0 = __float2half_rn(v0), h1 = __float2half_rn(v1);
    float l0 = v0 - __half2float(h0), l1 = v1 - __half2float(h1);
    __half2 hh = __halves2half2(h0, h1);
    hw = *reinterpret_cast<unsigned*>(&hh);
    lw = pack_h2(l0, l1);
}
__device__ __forceinline__ uint32_t smem_u32(const void* p) {
    uint32_t a;
    asm("{ .reg .u64 t; cvta.to.shared.u64 t, %1; cvt.u32.u64 %0, t; }" : "=r"(a) : "l"(p));
    return a;
}

#define CPASYNC16(dst, src) \
    asm volatile("cp.async.cg.shared.global [%0], [%1], 16;" :: "r"(dst), "l"(src))
#define MMA16816(d, a, b0, b1)                                                    \
    asm volatile("mma.sync.aligned.m16n8k16.row.col.f32.f16.f16.f32 "             \
                 "{%0,%1,%2,%3}, {%4,%5,%6,%7}, {%8,%9}, {%0,%1,%2,%3};"          \
                 : "+f"((d)[0]), "+f"((d)[1]), "+f"((d)[2]), "+f"((d)[3])         \
                 : "r"((a)[0]), "r"((a)[1]), "r"((a)[2]), "r"((a)[3]),            \
                   "r"(b0), "r"(b1))

// ---------------- prep0: detect + zero degi + prep B + x->fp16 (fused) ------
__global__ void prep0_kernel(const unsigned int* __restrict__ raw,
                             const float* __restrict__ x,
                             const float* __restrict__ Wl,
                             const float* __restrict__ Wr) {
    int b = blockIdx.x, t = threadIdx.x;
    if (b == 0) {
        __shared__ unsigned sacc[256];
        unsigned acc = 0;
        for (int j = t; j < 4096; j += 256) acc |= raw[2 * j + 1];
        sacc[t] = acc;
        __syncthreads();
        for (int s = 128; s > 0; s >>= 1) {
            if (t < s) sacc[t] |= sacc[t + s];
            __syncthreads();
        }
        if (t == 0) g_is32 = (sacc[0] != 0) ? 1 : 0;
    } else if (b < B0_PREPB) {
        int i = (b - B0_ZERO) * 256 + t;
        if (i < NN) g_degi[i] = 0;
    } else if (b < B0_XH) {
        // B precompute: [l][kpair(512)][n(512)] fp16 hi/lo pairs
        int u = (b - B0_PREPB) * 256 + t;          // < LL*512*512
        int n = u & 511;
        int kp = (u >> 9) & 511;
        int l = u >> 18;
        int k = 2 * kp;
        const float* W = (k < DD) ? (Wl + (size_t)l * DD * DD + (size_t)k * DD)
                                  : (Wr + (size_t)l * DD * DD + (size_t)(k - DD) * DD);
        float v0 = W[n], v1 = W[DD + n];
        unsigned hw, lw;
        split_pack_f16(v0, v1, hw, lw);
        size_t idx = ((size_t)l * 512 + kp) * 512 + n;
        g_Bh16[idx] = hw;
        g_Bl16[idx] = lw;
    } else {
        size_t w0 = ((size_t)(b - B0_XH) * 256 + t) * 8;
        if (w0 < (size_t)NN * 256) {
            const float2* xs = (const float2*)x + w0;
#pragma unroll
            for (int q = 0; q < 8; q++) {
                float2 f = xs[q];
                g_xh[w0 + q] = pack_h2(f.x, f.y);
            }
        }
    }
}

// ---------------- build ELL: decode edge, slot via atomicAdd ----------------
__global__ void build_ell_kernel(const void* __restrict__ raw,
                                 const float* __restrict__ ew) {
    int e = blockIdx.x * blockDim.x + threadIdx.x;
    if (e >= NE) return;
    int s, d;
    if (g_is32) {
        const int* p = (const int*)raw;
        s = p[e]; d = p[NE + e];
    } else {
        const long long* p = (const long long*)raw;
        s = (int)p[e]; d = (int)p[NE + e];
    }
    int slot = atomicAdd(&g_degi[d], 1);
    if (slot < PAD) {
        g_ell_src[(size_t)d * PAD + slot] = s;
        g_ell_w[(size_t)d * PAD + slot] = ew[e];
    }
}

// ---------------- gather: aggh[d] = pack_f16( mean_e w_e * z[src_e] ) -------
__global__ void __launch_bounds__(128) gather_kernel(int insel) {
    const uint32_t* zh = (insel == 0) ? g_xh : (insel == 1 ? g_zhA : g_zhB);
    int d = blockIdx.x, t = threadIdx.x;
    int deg = g_degi[d];
    int dg = (deg < PAD) ? deg : PAD;
    const int* esrc = g_ell_src + (size_t)d * PAD;
    const float* ewp = g_ell_w + (size_t)d * PAD;
    float4 a0 = make_float4(0.f, 0.f, 0.f, 0.f);
    float4 a1 = make_float4(0.f, 0.f, 0.f, 0.f);
    int j = 0;
    for (; j + 1 < dg; j += 2) {
        int s0 = __ldg(&esrc[j]);
        int s1 = __ldg(&esrc[j + 1]);
        float w0 = __ldg(&ewp[j]);
        float w1 = __ldg(&ewp[j + 1]);
        uint2 p0 = ((const uint2*)(zh + (size_t)s0 * 256))[t];
        uint2 p1 = ((const uint2*)(zh + (size_t)s1 * 256))[t];
        float2 u00 = __half22float2(*(__half2*)&p0.x);
        float2 u01 = __half22float2(*(__half2*)&p0.y);
        float2 u10 = __half22float2(*(__half2*)&p1.x);
        float2 u11 = __half22float2(*(__half2*)&p1.y);
        a0.x += w0 * u00.x; a0.y += w0 * u00.y;
        a0.z += w0 * u01.x; a0.w += w0 * u01.y;
        a1.x += w1 * u10.x; a1.y += w1 * u10.y;
        a1.z += w1 * u11.x; a1.w += w1 * u11.y;
    }
    if (j < dg) {
        int s0 = __ldg(&esrc[j]);
        float w0 = __ldg(&ewp[j]);
        uint2 p0 = ((const uint2*)(zh + (size_t)s0 * 256))[t];
        float2 u00 = __half22float2(*(__half2*)&p0.x);
        float2 u01 = __half22float2(*(__half2*)&p0.y);
        a0.x += w0 * u00.x; a0.y += w0 * u00.y;
        a0.z += w0 * u01.x; a0.w += w0 * u01.y;
    }
    float inv = (deg > 0) ? 1.0f / (float)deg : 0.0f;
    a0.x = (a0.x + a1.x) * inv;
    a0.y = (a0.y + a1.y) * inv;
    a0.z = (a0.z + a1.z) * inv;
    a0.w = (a0.w + a1.w) * inv;
    uint2 pk;
    pk.x = pack_h2(a0.x, a0.y);
    pk.y = pack_h2(a0.z, a0.w);
    ((uint2*)(g_aggh + (size_t)d * 256))[t] = pk;
}

// ---------------- GEMM: double-buffered streamed fp16 A+B, 2 CTAs/SM --------
__global__ void __launch_bounds__(256, 2) gemm_kernel(
    int zsel, int layer,
    const float* __restrict__ bias,
    float* __restrict__ outext, int outsel) {
    const uint32_t* zhin = (zsel == 0) ? g_xh : (zsel == 1 ? g_zhA : g_zhB);
    uint32_t* zhout = (outsel == 0) ? g_zhA : g_zhB;   // unused when outsel==2

    extern __shared__ uint32_t sw[];
    uint32_t sbase = smem_u32(sw);
    int tid = threadIdx.x, lane = tid & 31, warp = tid >> 5;
    int wm = warp >> 1, wn = warp & 1;          // 4x2 grid of 32x64 tiles
    int m0 = blockIdx.y * BM, n0 = blockIdx.x * BN;
    int g = lane >> 2, c = lane & 3;

    float acc[2][8][4];
#pragma unroll
    for (int i = 0; i < 2; i++)
#pragma unroll
        for (int j = 0; j < 8; j++)
#pragma unroll
            for (int q = 0; q < 4; q++) acc[i][j][q] = 0.0f;

    // A loader: thread -> (row ar = tid>>1, half ah = tid&1 -> 8 words)
    int ar = tid >> 1;
    int ah = tid & 1;
    int am = m0 + ar;
    int amc = (am < NN) ? am : (NN - 1);
    const uint32_t* Aagg = g_aggh + (size_t)amc * 256 + ah * 8;
    const uint32_t* Az   = zhin   + (size_t)amc * 256 + ah * 8;
    uint32_t a_dst0 = sbase + (A_W + ar * 20 + ah * 8) * 4;
    // B loader: thread -> (kpair bp = tid>>4 (0..15), word offset (tid&15)*8)
    int bp = tid >> 4;
    int bnw = (tid & 15) * 8;
    const uint32_t* Bh = g_Bh16 + ((size_t)layer * 512 + bp) * 512 + n0 + bnw;
    const uint32_t* Bl = g_Bl16 + ((size_t)layer * 512 + bp) * 512 + n0 + bnw;
    uint32_t bh_dst0 = sbase + (BHI_W + bp * 136 + bnw) * 4;
    uint32_t bl_dst0 = sbase + (BLO_W + bp * 136 + bnw) * 4;

    auto issue_copy = [&](int kc, int s) {
        uint32_t soff = (uint32_t)s * (SLOT_W * 4);
        const uint32_t* as = (kc < 16) ? (Aagg + kc * 16) : (Az + (kc - 16) * 16);
        CPASYNC16(a_dst0 + soff, as);
        CPASYNC16(a_dst0 + soff + 16, as + 4);
        const uint32_t* bh = Bh + (size_t)kc * (16 * 512);
        const uint32_t* bl = Bl + (size_t)kc * (16 * 512);
        CPASYNC16(bh_dst0 + soff, bh);
        CPASYNC16(bh_dst0 + soff + 16, bh + 4);
        CPASYNC16(bl_dst0 + soff, bl);
        CPASYNC16(bl_dst0 + soff + 16, bl + 4);
        asm volatile("cp.async.commit_group;");
    };

    issue_copy(0, 0);

    for (int kc = 0; kc < NCHK; kc++) {
        int s = kc & 1;
        __syncthreads();   // all warps done computing slot 1-s (chunk kc-1)
        if (kc + 1 < NCHK) {
            issue_copy(kc + 1, 1 - s);
            asm volatile("cp.async.wait_group 1;");   // chunk kc's copy done
        } else {
            asm volatile("cp.async.wait_group 0;");
        }
        __syncthreads();
        // ---- compute slot s: 2 x k16, 2 products each (warp tile 32x64)
        uint32_t so = (uint32_t)s * SLOT_W;
#pragma unroll
        for (int ks = 0; ks < 2; ks++) {
            int ab = so + A_W + (wm * 32 + g) * 20 + 8 * ks + c;
            int bb = so + (8 * ks + c) * 136 + wn * 64 + g;
            uint32_t af[2][4], bf2[4][4];
#pragma unroll
            for (int i = 0; i < 2; i++) {
                int x = ab + i * 320;        // row + 16i
                af[i][0] = sw[x];            // (row, kp)
                af[i][1] = sw[x + 160];      // (row+8, kp)
                af[i][2] = sw[x + 4];        // (row, kp+4)
                af[i][3] = sw[x + 164];      // (row+8, kp+4)
            }
            // P1: Ahi x Bhi
#pragma unroll
            for (int j = 0; j < 4; j++) {
                int x = BHI_W + bb + j * 16;
                bf2[j][0] = sw[x]; bf2[j][1] = sw[x + 544];
                bf2[j][2] = sw[x + 8]; bf2[j][3] = sw[x + 552];
            }
#pragma unroll
            for (int i = 0; i < 2; i++)
#pragma unroll
                for (int j = 0; j < 4; j++) {
                    MMA16816(acc[i][2 * j], af[i], bf2[j][0], bf2[j][1]);
                    MMA16816(acc[i][2 * j + 1], af[i], bf2[j][2], bf2[j][3]);
                }
            // P2: Ahi x Blo
#pragma unroll
            for (int j = 0; j < 4; j++) {
                int x = BLO_W + bb + j * 16 - BHI_W + BHI_W;  // keep form
                x = BLO_W + bb + j * 16;
                bf2[j][0] = sw[x]; bf2[j][1] = sw[x + 544];
                bf2[j][2] = sw[x + 8]; bf2[j][3] = sw[x + 552];
            }
#pragma unroll
            for (int i = 0; i < 2; i++)
#pragma unroll
                for (int j = 0; j < 4; j++) {
                    MMA16816(acc[i][2 * j], af[i], bf2[j][0], bf2[j][1]);
                    MMA16816(acc[i][2 * j + 1], af[i], bf2[j][2], bf2[j][3]);
                }
        }
    }

    // ---- epilogue: bias + relu; fp16-pair z (or fp32 out on last layer)
    int cc = c << 1;
    float bj0[8], bj1[8];
#pragma unroll
    for (int j = 0; j < 8; j++) {
        int col = n0 + wn * 64 + j * 8 + cc;
        bj0[j] = __ldg(bias + col);
        bj1[j] = __ldg(bias + col + 1);
    }
#pragma unroll
    for (int i = 0; i < 2; i++) {
        int r0 = m0 + wm * 32 + i * 16 + g;
#pragma unroll
        for (int j = 0; j < 8; j++) {
            int col = n0 + wn * 64 + j * 8 + cc;
            float v00 = fmaxf(acc[i][j][0] + bj0[j], 0.0f);
            float v01 = fmaxf(acc[i][j][1] + bj1[j], 0.0f);
            float v10 = fmaxf(acc[i][j][2] + bj0[j], 0.0f);
            float v11 = fmaxf(acc[i][j][3] + bj1[j], 0.0f);
            if (outsel == 2) {
                if (r0 < NN)
                    *(float2*)(outext + (size_t)r0 * DD + col) = make_float2(v00, v01);
                if (r0 + 8 < NN)
                    *(float2*)(outext + (size_t)(r0 + 8) * DD + col) = make_float2(v10, v11);
            } else {
                if (r0 < NN)
                    zhout[(size_t)r0 * 256 + (col >> 1)] = pack_h2(v00, v01);
                if (r0 + 8 < NN)
                    zhout[(size_t)(r0 + 8) * 256 + (col >> 1)] = pack_h2(v10, v11);
            }
        }
    }
}

// ---------------- launch ----------------
extern "C" void kernel_launch(void* const* d_in, const int* in_sizes, int n_in,
                              void* d_out, int out_size) {
    (void)in_sizes; (void)n_in; (void)out_size;
    const float* x  = (const float*)d_in[0];
    const void*  ei = d_in[1];
    const float* ew = (const float*)d_in[2];
    const float* Wl = (const float*)d_in[3];
    const float* Wr = (const float*)d_in[4];
    const float* b  = (const float*)d_in[5];
    float* out = (float*)d_out;

    cudaFuncSetAttribute(gemm_kernel, cudaFuncAttributeMaxDynamicSharedMemorySize, SMEM_BYTES);

    prep0_kernel<<<B0_TOTAL, 256>>>((const unsigned int*)ei, x, Wl, Wr);
    build_ell_kernel<<<(NE + 255) / 256, 256>>>(ei, ew);

    dim3 ggrid(4, (NN + BM - 1) / BM);   // n-blocks x m-tiles

    // z chain: xh -> zhA -> zhB -> out(fp32)
    for (int l = 0; l < LL; l++) {
        int zsel   = l;                      // 0:xh 1:zhA 2:zhB
        int outsel = (l == LL - 1) ? 2 : l;  // 0:zhA 1:zhB 2:external fp32
        gather_kernel<<<NN, 128>>>(zsel);
        gemm_kernel<<<ggrid, 256, SMEM_BYTES>>>(zsel, l,
                                                b + (size_t)l * DD,
                                                out, outsel);
    }
}